// round 8
// baseline (speedup 1.0000x reference)
#include <cuda_runtime.h>
#include <math.h>

// ---------------------------------------------------------------------------
// Problem constants
// ---------------------------------------------------------------------------
#define BATCH   4
#define SEQ     4096
#define DMODEL  768
#define DFF     3072
#define NHEAD   8
#define HDIM    96
#define BLK     64
#define NBLOCKS (SEQ / BLK)        // 64
#define MKB     7                  // key blocks per query block
#define ROWS    (BATCH * SEQ)      // 16384

// ---------------------------------------------------------------------------
// Scratch (static __device__ arrays: allocation-free per harness rules)
// ---------------------------------------------------------------------------
__device__ float g_x1  [ROWS * DMODEL];   // LN1 output
__device__ float g_q   [ROWS * DMODEL];
__device__ float g_k   [ROWS * DMODEL];
__device__ float g_v   [ROWS * DMODEL];
__device__ float g_att [ROWS * DMODEL];   // attention output (pre-Wo)
__device__ float g_x   [ROWS * DMODEL];   // residual stream after attn
__device__ float g_h   [ROWS * DMODEL];   // LN2 output
__device__ float g_ffn [ROWS * DFF];      // gelu(h@W1+b1)

// ---------------------------------------------------------------------------
// LayerNorm: one block per row, 256 threads, D=768 -> 3 elems/thread
// ---------------------------------------------------------------------------
__global__ void __launch_bounds__(256) ln_kernel(
    const float* __restrict__ x, const float* __restrict__ g,
    const float* __restrict__ b, float* __restrict__ y)
{
    const int row = blockIdx.x;
    const float* xr = x + (size_t)row * DMODEL;
    float*       yr = y + (size_t)row * DMODEL;
    const int t = threadIdx.x;

    float v0 = xr[t], v1 = xr[t + 256], v2 = xr[t + 512];

    __shared__ float red1[8], red2[8];

    float s = v0 + v1 + v2;
    #pragma unroll
    for (int o = 16; o; o >>= 1) s += __shfl_xor_sync(0xffffffffu, s, o);
    if ((t & 31) == 0) red1[t >> 5] = s;
    __syncthreads();
    float tot = 0.f;
    #pragma unroll
    for (int i = 0; i < 8; ++i) tot += red1[i];
    const float mean = tot * (1.0f / DMODEL);

    float d0 = v0 - mean, d1 = v1 - mean, d2 = v2 - mean;
    float sq = d0 * d0 + d1 * d1 + d2 * d2;
    #pragma unroll
    for (int o = 16; o; o >>= 1) sq += __shfl_xor_sync(0xffffffffu, sq, o);
    if ((t & 31) == 0) red2[t >> 5] = sq;
    __syncthreads();
    float tot2 = 0.f;
    #pragma unroll
    for (int i = 0; i < 8; ++i) tot2 += red2[i];
    const float rstd = rsqrtf(tot2 * (1.0f / DMODEL) + 1e-5f);

    yr[t      ] = d0 * rstd * g[t      ] + b[t      ];
    yr[t + 256] = d1 * rstd * g[t + 256] + b[t + 256];
    yr[t + 512] = d2 * rstd * g[t + 512] + b[t + 512];
}

// ---------------------------------------------------------------------------
// SGEMM: C[M,N] = A[M,K] @ B[K,N] + bias (+ residual) (+ gelu)
// 128x128 tile, BK=8, 256 threads, 8x8 per-thread micro-tile, double buffered.
// ---------------------------------------------------------------------------
__device__ __forceinline__ float gelu_tanh(float x)
{
    // jax.nn.gelu default (approximate=True)
    const float c = 0.7978845608028654f;   // sqrt(2/pi)
    float x3 = x * x * x;
    return 0.5f * x * (1.0f + tanhf(c * (x + 0.044715f * x3)));
}

template <bool GELU, bool RES>
__global__ void __launch_bounds__(256, 2) sgemm_kernel(
    const float* __restrict__ A, const float* __restrict__ B,
    const float* __restrict__ bias, const float* __restrict__ R,
    float* __restrict__ C, int M, int N, int K)
{
    __shared__ float As[2][8][132];   // [k][m], padded vs bank conflicts
    __shared__ float Bs[2][8][128];   // [k][n]

    const int tid = threadIdx.x;
    const int tx  = tid & 15;         // 16 col-threads
    const int ty  = tid >> 4;         // 16 row-threads
    const int bm  = blockIdx.y * 128;
    const int bn  = blockIdx.x * 128;

    const int arow = tid >> 1;            // 0..127
    const int acol = (tid & 1) << 2;      // 0 or 4
    const int brow = tid >> 5;            // 0..7
    const int bcol = (tid & 31) << 2;     // 0..124

    const float* Ap = A + (size_t)(bm + arow) * K + acol;
    const float* Bp = B + (size_t)brow * N + bn + bcol;

    // prologue: tile 0
    {
        float4 a  = *(const float4*)(Ap);
        float4 b4 = *(const float4*)(Bp);
        As[0][acol + 0][arow] = a.x;
        As[0][acol + 1][arow] = a.y;
        As[0][acol + 2][arow] = a.z;
        As[0][acol + 3][arow] = a.w;
        *(float4*)&Bs[0][brow][bcol] = b4;
    }
    __syncthreads();

    float acc[8][8];
    #pragma unroll
    for (int i = 0; i < 8; ++i)
        #pragma unroll
        for (int j = 0; j < 8; ++j) acc[i][j] = 0.f;

    const int kt = K >> 3;
    for (int t = 0; t < kt; ++t) {
        const int cur = t & 1;
        float4 an, bn4;
        const bool has_next = (t + 1 < kt);
        if (has_next) {
            an  = *(const float4*)(Ap + (t + 1) * 8);
            bn4 = *(const float4*)(Bp + (size_t)(t + 1) * 8 * N);
        }

        #pragma unroll
        for (int k = 0; k < 8; ++k) {
            float af[8], bf[8];
            *(float4*)(af    ) = *(const float4*)&As[cur][k][ty * 8];
            *(float4*)(af + 4) = *(const float4*)&As[cur][k][ty * 8 + 4];
            *(float4*)(bf    ) = *(const float4*)&Bs[cur][k][tx * 8];
            *(float4*)(bf + 4) = *(const float4*)&Bs[cur][k][tx * 8 + 4];
            #pragma unroll
            for (int i = 0; i < 8; ++i)
                #pragma unroll
                for (int j = 0; j < 8; ++j)
                    acc[i][j] += af[i] * bf[j];
        }

        if (has_next) {
            const int nxt = cur ^ 1;
            As[nxt][acol + 0][arow] = an.x;
            As[nxt][acol + 1][arow] = an.y;
            As[nxt][acol + 2][arow] = an.z;
            As[nxt][acol + 3][arow] = an.w;
            *(float4*)&Bs[nxt][brow][bcol] = bn4;
        }
        __syncthreads();
    }

    // epilogue
    #pragma unroll
    for (int i = 0; i < 8; ++i) {
        const int row = bm + ty * 8 + i;
        #pragma unroll
        for (int j4 = 0; j4 < 2; ++j4) {
            const int col = bn + tx * 8 + j4 * 4;
            float4 v;
            v.x = acc[i][j4 * 4 + 0] + bias[col + 0];
            v.y = acc[i][j4 * 4 + 1] + bias[col + 1];
            v.z = acc[i][j4 * 4 + 2] + bias[col + 2];
            v.w = acc[i][j4 * 4 + 3] + bias[col + 3];
            if (GELU) {
                v.x = gelu_tanh(v.x); v.y = gelu_tanh(v.y);
                v.z = gelu_tanh(v.z); v.w = gelu_tanh(v.w);
            }
            if (RES) {
                float4 r = *(const float4*)(R + (size_t)row * N + col);
                v.x += r.x; v.y += r.y; v.z += r.z; v.w += r.w;
            }
            *(float4*)(C + (size_t)row * N + col) = v;
        }
    }
}

// ---------------------------------------------------------------------------
// BigBird block-sparse attention, flash-style online softmax.
//
// IMPORTANT reference quirk replicated here: the reference's broadcast
//   mask = valid[:, :, None] & (kpos <= qpos)
// aligns valid's nb axis with the *q-row* axis (nb == BLOCK == 64). So slot m
// of query-row q is valid iff key_block_idx[q, m] >= 0 (row-indexed), while
// the gathered key block is idx = max(key_block_idx[n, m], 0) (block-indexed,
// clamped: padded slots read block 0 and still enter the softmax when the
// row-indexed validity allows it).
//
// Grid: (nb=64, H=8, b=4). 256 threads: r = tid>>2 (row 0..63), sub = tid&3.
// ---------------------------------------------------------------------------
#define KS_STRIDE 100
#define PS_STRIDE 68

__global__ void __launch_bounds__(256, 2) attn_kernel(
    const float* __restrict__ Q, const float* __restrict__ K,
    const float* __restrict__ V, const int* __restrict__ kbi,
    float* __restrict__ O)
{
    extern __shared__ float sm[];
    float* qs = sm;                               // 64*96   = 6144
    float* ks = sm + 6144;                        // 64*100  = 6400
    float* vs = sm + 6144 + 6400;                 // 64*100  = 6400
    float* ps = sm + 6144 + 6400 + 6400;          // 64*68   = 4352

    __shared__ int skbi[NBLOCKS * MKB];           // full 64x7 table (1792 B)

    const int qb = blockIdx.x;
    const int h  = blockIdx.y;
    const int bi = blockIdx.z;
    const int tid = threadIdx.x;
    const int r   = tid >> 2;
    const int sub = tid & 3;

    const int   row0 = bi * SEQ + qb * BLK;
    const int   coff = h * HDIM;
    const float scale = rsqrtf((float)HDIM);      // 1/sqrt(96)

    // preload the whole key_block_idx table
    for (int i = tid; i < NBLOCKS * MKB; i += 256) skbi[i] = kbi[i];

    // load Q tile (64 x 96), coalesced float4
    {
        const float4* Qg = (const float4*)(Q + (size_t)row0 * DMODEL + coff);
        for (int idx = tid; idx < 64 * 24; idx += 256) {
            int rr = idx / 24, c4 = idx % 24;
            float4 v = Qg[(size_t)rr * (DMODEL / 4) + c4];
            *(float4*)&qs[rr * HDIM + c4 * 4] = v;
        }
    }
    __syncthreads();

    float acc[24];
    #pragma unroll
    for (int c = 0; c < 24; ++c) acc[c] = 0.f;
    float m_i = -INFINITY, l_i = 0.f;

    const int  qpos = qb * BLK + r;
    const float4* qs4 = (const float4*)qs;

    for (int kb = 0; kb < MKB; ++kb) {
        // key block gathered with clamped (block-indexed) idx
        const int kraw = skbi[qb * MKB + kb];
        const int jdx  = kraw > 0 ? kraw : 0;
        // validity is ROW-indexed (reference broadcast quirk)
        const bool vrow = (skbi[r * MKB + kb] >= 0);

        __syncthreads();                          // protect ks/vs reuse
        {
            const size_t base = (size_t)(bi * SEQ + jdx * BLK) * DMODEL + coff;
            const float4* Kg = (const float4*)(K + base);
            const float4* Vg = (const float4*)(V + base);
            for (int idx = tid; idx < 64 * 24; idx += 256) {
                int rr = idx / 24, c4 = idx % 24;
                *(float4*)&ks[rr * KS_STRIDE + c4 * 4] =
                    Kg[(size_t)rr * (DMODEL / 4) + c4];
                *(float4*)&vs[rr * KS_STRIDE + c4 * 4] =
                    Vg[(size_t)rr * (DMODEL / 4) + c4];
            }
        }
        __syncthreads();

        // scores: 16 cols per thread (col = sub + 4*j)
        float s[16];
        #pragma unroll
        for (int j = 0; j < 16; ++j) s[j] = 0.f;
        #pragma unroll 4
        for (int d4 = 0; d4 < 24; ++d4) {
            float4 qv = qs4[r * 24 + d4];
            #pragma unroll
            for (int j = 0; j < 16; ++j) {
                const int col = sub + 4 * j;
                float4 kv = *(const float4*)&ks[col * KS_STRIDE + d4 * 4];
                s[j] += qv.x * kv.x + qv.y * kv.y + qv.z * kv.z + qv.w * kv.w;
            }
        }

        // scale + mask (row validity & causal) + local max
        float mloc = -INFINITY;
        #pragma unroll
        for (int j = 0; j < 16; ++j) {
            const int col  = sub + 4 * j;
            const int kpos = jdx * BLK + col;
            s[j] *= scale;
            if (!vrow || kpos > qpos) s[j] = -1e9f;
            mloc = fmaxf(mloc, s[j]);
        }
        mloc = fmaxf(mloc, __shfl_xor_sync(0xffffffffu, mloc, 1));
        mloc = fmaxf(mloc, __shfl_xor_sync(0xffffffffu, mloc, 2));

        const float mnew  = fmaxf(m_i, mloc);
        const float alpha = __expf(m_i - mnew);   // expf(-inf)=0 on first block

        float psum = 0.f;
        #pragma unroll
        for (int j = 0; j < 16; ++j) {
            const float p = __expf(s[j] - mnew);
            ps[r * PS_STRIDE + sub + 4 * j] = p;
            psum += p;
        }
        psum += __shfl_xor_sync(0xffffffffu, psum, 1);
        psum += __shfl_xor_sync(0xffffffffu, psum, 2);

        l_i = l_i * alpha + psum;
        m_i = mnew;
        #pragma unroll
        for (int c = 0; c < 24; ++c) acc[c] *= alpha;

        __syncwarp();    // p exchange is within-warp (4 lanes per row)

        // acc += P @ V   (64 key positions x 24 owned cols)
        #pragma unroll 4
        for (int j = 0; j < 64; ++j) {
            const float p = ps[r * PS_STRIDE + j];
            #pragma unroll
            for (int c4 = 0; c4 < 6; ++c4) {
                float4 vv = *(const float4*)&vs[j * KS_STRIDE + sub * 24 + c4 * 4];
                acc[c4 * 4 + 0] += p * vv.x;
                acc[c4 * 4 + 1] += p * vv.y;
                acc[c4 * 4 + 2] += p * vv.z;
                acc[c4 * 4 + 3] += p * vv.w;
            }
        }
    }

    const float inv = 1.0f / l_i;
    float* Og = O + (size_t)(row0 + r) * DMODEL + coff + sub * 24;
    #pragma unroll
    for (int c4 = 0; c4 < 6; ++c4) {
        float4 v;
        v.x = acc[c4 * 4 + 0] * inv;
        v.y = acc[c4 * 4 + 1] * inv;
        v.z = acc[c4 * 4 + 2] * inv;
        v.w = acc[c4 * 4 + 3] * inv;
        *(float4*)(Og + c4 * 4) = v;
    }
}

// ---------------------------------------------------------------------------
// Launch
// ---------------------------------------------------------------------------
extern "C" void kernel_launch(void* const* d_in, const int* in_sizes, int n_in,
                              void* d_out, int out_size)
{
    const float* q     = (const float*)d_in[0];
    const float* ln1_g = (const float*)d_in[1];
    const float* ln1_b = (const float*)d_in[2];
    const float* Wq    = (const float*)d_in[3];
    const float* bq    = (const float*)d_in[4];
    const float* Wk    = (const float*)d_in[5];
    const float* bk    = (const float*)d_in[6];
    const float* Wv    = (const float*)d_in[7];
    const float* bv    = (const float*)d_in[8];
    const float* Wo    = (const float*)d_in[9];
    const float* bo    = (const float*)d_in[10];
    const float* ln2_g = (const float*)d_in[11];
    const float* ln2_b = (const float*)d_in[12];
    const float* W1    = (const float*)d_in[13];
    const float* b1    = (const float*)d_in[14];
    const float* W2    = (const float*)d_in[15];
    const float* b2    = (const float*)d_in[16];
    const int*   kbi   = (const int*)d_in[17];
    float* out = (float*)d_out;

    float *x1, *qb, *kb, *vb, *att, *xb, *hb, *gb;
    cudaGetSymbolAddress((void**)&x1,  g_x1);
    cudaGetSymbolAddress((void**)&qb,  g_q);
    cudaGetSymbolAddress((void**)&kb,  g_k);
    cudaGetSymbolAddress((void**)&vb,  g_v);
    cudaGetSymbolAddress((void**)&att, g_att);
    cudaGetSymbolAddress((void**)&xb,  g_x);
    cudaGetSymbolAddress((void**)&hb,  g_h);
    cudaGetSymbolAddress((void**)&gb,  g_ffn);

    const int ATTN_SMEM = (6144 + 6400 + 6400 + 4352) * 4;   // 93184 B
    cudaFuncSetAttribute(attn_kernel,
                         cudaFuncAttributeMaxDynamicSharedMemorySize, ATTN_SMEM);

    // 1. x1 = LN1(q)
    ln_kernel<<<ROWS, 256>>>(q, ln1_g, ln1_b, x1);

    // 2. Q,K,V projections
    dim3 gp(DMODEL / 128, ROWS / 128);
    sgemm_kernel<false, false><<<gp, 256>>>(x1, Wq, bq, nullptr, qb, ROWS, DMODEL, DMODEL);
    sgemm_kernel<false, false><<<gp, 256>>>(x1, Wk, bk, nullptr, kb, ROWS, DMODEL, DMODEL);
    sgemm_kernel<false, false><<<gp, 256>>>(x1, Wv, bv, nullptr, vb, ROWS, DMODEL, DMODEL);

    // 3. BigBird attention
    attn_kernel<<<dim3(NBLOCKS, NHEAD, BATCH), 256, ATTN_SMEM>>>(qb, kb, vb, kbi, att);

    // 4. x = q + att @ Wo + bo
    sgemm_kernel<false, true><<<gp, 256>>>(att, Wo, bo, q, xb, ROWS, DMODEL, DMODEL);

    // 5. h = LN2(x)
    ln_kernel<<<ROWS, 256>>>(xb, ln2_g, ln2_b, hb);

    // 6. g = gelu(h @ W1 + b1)
    dim3 g1(DFF / 128, ROWS / 128);
    sgemm_kernel<true, false><<<g1, 256>>>(hb, W1, b1, nullptr, gb, ROWS, DFF, DMODEL);

    // 7. out = x + g @ W2 + b2
    sgemm_kernel<false, true><<<gp, 256>>>(gb, W2, b2, xb, out, ROWS, DMODEL, DFF);
}

// round 9
// speedup vs baseline: 1.3036x; 1.3036x over previous
#include <cuda_runtime.h>
#include <math.h>
#include <stdint.h>

// ---------------------------------------------------------------------------
// Problem constants
// ---------------------------------------------------------------------------
#define BATCH   4
#define SEQ     4096
#define DMODEL  768
#define DFF     3072
#define NHEAD   8
#define HDIM    96
#define BLK     64
#define NBLOCKS (SEQ / BLK)        // 64
#define MKB     7                  // key blocks per query block
#define ROWS    (BATCH * SEQ)      // 16384

// ---------------------------------------------------------------------------
// Scratch (static __device__ arrays: allocation-free per harness rules)
// ---------------------------------------------------------------------------
__device__ float g_x1  [ROWS * DMODEL];   // LN1 output
__device__ float g_q   [ROWS * DMODEL];
__device__ float g_k   [ROWS * DMODEL];
__device__ float g_v   [ROWS * DMODEL];
__device__ float g_att [ROWS * DMODEL];   // attention output (pre-Wo)
__device__ float g_x   [ROWS * DMODEL];   // residual stream after attn
__device__ float g_h   [ROWS * DMODEL];   // LN2 output
__device__ float g_ffn [ROWS * DFF];      // gelu(h@W1+b1)

// ---------------------------------------------------------------------------
// LayerNorm: one block per row, 256 threads, D=768 -> 3 elems/thread
// ---------------------------------------------------------------------------
__global__ void __launch_bounds__(256) ln_kernel(
    const float* __restrict__ x, const float* __restrict__ g,
    const float* __restrict__ b, float* __restrict__ y)
{
    const int row = blockIdx.x;
    const float* xr = x + (size_t)row * DMODEL;
    float*       yr = y + (size_t)row * DMODEL;
    const int t = threadIdx.x;

    float v0 = xr[t], v1 = xr[t + 256], v2 = xr[t + 512];

    __shared__ float red1[8], red2[8];

    float s = v0 + v1 + v2;
    #pragma unroll
    for (int o = 16; o; o >>= 1) s += __shfl_xor_sync(0xffffffffu, s, o);
    if ((t & 31) == 0) red1[t >> 5] = s;
    __syncthreads();
    float tot = 0.f;
    #pragma unroll
    for (int i = 0; i < 8; ++i) tot += red1[i];
    const float mean = tot * (1.0f / DMODEL);

    float d0 = v0 - mean, d1 = v1 - mean, d2 = v2 - mean;
    float sq = d0 * d0 + d1 * d1 + d2 * d2;
    #pragma unroll
    for (int o = 16; o; o >>= 1) sq += __shfl_xor_sync(0xffffffffu, sq, o);
    if ((t & 31) == 0) red2[t >> 5] = sq;
    __syncthreads();
    float tot2 = 0.f;
    #pragma unroll
    for (int i = 0; i < 8; ++i) tot2 += red2[i];
    const float rstd = rsqrtf(tot2 * (1.0f / DMODEL) + 1e-5f);

    yr[t      ] = d0 * rstd * g[t      ] + b[t      ];
    yr[t + 256] = d1 * rstd * g[t + 256] + b[t + 256];
    yr[t + 512] = d2 * rstd * g[t + 512] + b[t + 512];
}

// ---------------------------------------------------------------------------
// tf32 tensor-core GEMM: C[M,N] = A[M,K] @ B[K,N] + bias (+gelu) (+residual)
// 128x128x16 CTA tile, 8 warps (warp tile 32x64), mma.sync.m16n8k8.tf32,
// cp.async double-buffered fp32 smem, rna tf32 conversion on fragments.
// ---------------------------------------------------------------------------
__device__ __forceinline__ float gelu_tanh(float x)
{
    const float c = 0.7978845608028654f;   // sqrt(2/pi)
    float x3 = x * x * x;
    return 0.5f * x * (1.0f + tanhf(c * (x + 0.044715f * x3)));
}

__device__ __forceinline__ uint32_t f2tf32(float x)
{
    uint32_t r;
    asm("cvt.rna.tf32.f32 %0, %1;" : "=r"(r) : "f"(x));
    return r;
}

__device__ __forceinline__ void cp16(void* s, const void* g)
{
    uint32_t sa = (uint32_t)__cvta_generic_to_shared(s);
    asm volatile("cp.async.cg.shared.global [%0], [%1], 16;" :: "r"(sa), "l"(g));
}
#define CP_COMMIT() asm volatile("cp.async.commit_group;")
#define CP_WAIT1()  asm volatile("cp.async.wait_group 1;")

__device__ __forceinline__ void mma_tf32(float4& d,
    uint32_t a0, uint32_t a1, uint32_t a2, uint32_t a3,
    uint32_t b0, uint32_t b1)
{
    asm("mma.sync.aligned.m16n8k8.row.col.f32.tf32.tf32.f32 "
        "{%0,%1,%2,%3}, {%4,%5,%6,%7}, {%8,%9}, {%0,%1,%2,%3};"
        : "+f"(d.x), "+f"(d.y), "+f"(d.z), "+f"(d.w)
        : "r"(a0), "r"(a1), "r"(a2), "r"(a3), "r"(b0), "r"(b1));
}

#define AS_STR 20    // padded A row stride (conflict-free fragment loads)
#define BS_STR 136   // padded B row stride (conflict-free fragment loads)

template <bool GELU, bool RES>
__global__ void __launch_bounds__(256, 2) mma_gemm_kernel(
    const float* __restrict__ A, const float* __restrict__ B,
    const float* __restrict__ bias, const float* __restrict__ R,
    float* __restrict__ C, int M, int N, int K)
{
    __shared__ float As[2][128][AS_STR];   // [buf][m][k]
    __shared__ float Bs[2][16][BS_STR];    // [buf][k][n]

    const int tid  = threadIdx.x;
    const int lane = tid & 31;
    const int warp = tid >> 5;
    const int wm   = warp & 3;     // 0..3 : 32-row slab
    const int wn   = warp >> 2;    // 0..1 : 64-col slab
    const int lq   = lane & 3;
    const int lh   = lane >> 2;
    const int bm   = blockIdx.y * 128;
    const int bn   = blockIdx.x * 128;

    // staging indices
    const int ar = tid >> 2, ac = (tid & 3) << 2;     // A: 64 rows/pass, 16 cols
    const int br = tid >> 5, bc = (tid & 31) << 2;    // B: 8 rows/pass, 128 cols

    const float* Abase = A + (size_t)(bm + ar) * K + ac;
    const float* Bbase = B + (size_t)br * N + bn + bc;

    // prologue: stage tile 0
    cp16(&As[0][ar     ][ac], Abase);
    cp16(&As[0][ar + 64][ac], Abase + (size_t)64 * K);
    cp16(&Bs[0][br     ][bc], Bbase);
    cp16(&Bs[0][br +  8][bc], Bbase + (size_t)8 * N);
    CP_COMMIT();

    float4 acc[2][8];
    #pragma unroll
    for (int i = 0; i < 2; ++i)
        #pragma unroll
        for (int j = 0; j < 8; ++j) acc[i][j] = make_float4(0.f, 0.f, 0.f, 0.f);

    const int kt = K >> 4;
    for (int t = 0; t < kt; ++t) {
        // stage next tile
        if (t + 1 < kt) {
            const int nb = (t + 1) & 1;
            const int k0 = (t + 1) << 4;
            cp16(&As[nb][ar     ][ac], Abase + k0);
            cp16(&As[nb][ar + 64][ac], Abase + k0 + (size_t)64 * K);
            cp16(&Bs[nb][br     ][bc], Bbase + (size_t)k0 * N);
            cp16(&Bs[nb][br +  8][bc], Bbase + (size_t)(k0 + 8) * N);
        }
        CP_COMMIT();
        CP_WAIT1();           // tile t resident
        __syncthreads();

        const int cb = t & 1;
        #pragma unroll
        for (int ks = 0; ks < 2; ++ks) {
            const int k0 = ks << 3;
            uint32_t af[2][4], bf[8][2];
            #pragma unroll
            for (int mt = 0; mt < 2; ++mt) {
                const int m = wm * 32 + mt * 16 + lh;
                af[mt][0] = f2tf32(As[cb][m    ][k0     + lq]);
                af[mt][1] = f2tf32(As[cb][m + 8][k0     + lq]);
                af[mt][2] = f2tf32(As[cb][m    ][k0 + 4 + lq]);
                af[mt][3] = f2tf32(As[cb][m + 8][k0 + 4 + lq]);
            }
            #pragma unroll
            for (int nt = 0; nt < 8; ++nt) {
                const int n = wn * 64 + nt * 8 + lh;
                bf[nt][0] = f2tf32(Bs[cb][k0     + lq][n]);
                bf[nt][1] = f2tf32(Bs[cb][k0 + 4 + lq][n]);
            }
            #pragma unroll
            for (int mt = 0; mt < 2; ++mt)
                #pragma unroll
                for (int nt = 0; nt < 8; ++nt)
                    mma_tf32(acc[mt][nt], af[mt][0], af[mt][1], af[mt][2],
                             af[mt][3], bf[nt][0], bf[nt][1]);
        }
        __syncthreads();      // protect buf t&1 before it is restaged
    }

    // epilogue: c0,c1 at (row, col..col+1); c2,c3 at (row+8, ...)
    #pragma unroll
    for (int mt = 0; mt < 2; ++mt) {
        const int row = bm + wm * 32 + mt * 16 + lh;
        #pragma unroll
        for (int nt = 0; nt < 8; ++nt) {
            const int col = bn + wn * 64 + nt * 8 + lq * 2;
            const float2 bb = *(const float2*)(bias + col);

            float2 v0 = make_float2(acc[mt][nt].x + bb.x, acc[mt][nt].y + bb.y);
            float2 v1 = make_float2(acc[mt][nt].z + bb.x, acc[mt][nt].w + bb.y);
            if (GELU) {
                v0.x = gelu_tanh(v0.x); v0.y = gelu_tanh(v0.y);
                v1.x = gelu_tanh(v1.x); v1.y = gelu_tanh(v1.y);
            }
            if (RES) {
                float2 r0 = *(const float2*)(R + (size_t)row * N + col);
                float2 r1 = *(const float2*)(R + (size_t)(row + 8) * N + col);
                v0.x += r0.x; v0.y += r0.y;
                v1.x += r1.x; v1.y += r1.y;
            }
            *(float2*)(C + (size_t)row * N + col)       = v0;
            *(float2*)(C + (size_t)(row + 8) * N + col) = v1;
        }
    }
}

// ---------------------------------------------------------------------------
// BigBird block-sparse attention, flash-style online softmax (fp32).
// Reference broadcast quirk replicated: slot validity is ROW-indexed
// (key_block_idx[q_row, m] >= 0) while the gathered block index is
// max(key_block_idx[q_block, m], 0).
// ---------------------------------------------------------------------------
#define KS_STRIDE 100
#define PS_STRIDE 68

__global__ void __launch_bounds__(256, 2) attn_kernel(
    const float* __restrict__ Q, const float* __restrict__ K,
    const float* __restrict__ V, const int* __restrict__ kbi,
    float* __restrict__ O)
{
    extern __shared__ float sm[];
    float* qs = sm;                               // 64*96   = 6144
    float* ks = sm + 6144;                        // 64*100  = 6400
    float* vs = sm + 6144 + 6400;                 // 64*100  = 6400
    float* ps = sm + 6144 + 6400 + 6400;          // 64*68   = 4352

    __shared__ int skbi[NBLOCKS * MKB];

    const int qb = blockIdx.x;
    const int h  = blockIdx.y;
    const int bi = blockIdx.z;
    const int tid = threadIdx.x;
    const int r   = tid >> 2;
    const int sub = tid & 3;

    const int   row0 = bi * SEQ + qb * BLK;
    const int   coff = h * HDIM;
    const float scale = rsqrtf((float)HDIM);

    for (int i = tid; i < NBLOCKS * MKB; i += 256) skbi[i] = kbi[i];

    {
        const float4* Qg = (const float4*)(Q + (size_t)row0 * DMODEL + coff);
        for (int idx = tid; idx < 64 * 24; idx += 256) {
            int rr = idx / 24, c4 = idx % 24;
            float4 v = Qg[(size_t)rr * (DMODEL / 4) + c4];
            *(float4*)&qs[rr * HDIM + c4 * 4] = v;
        }
    }
    __syncthreads();

    float acc[24];
    #pragma unroll
    for (int c = 0; c < 24; ++c) acc[c] = 0.f;
    float m_i = -INFINITY, l_i = 0.f;

    const int  qpos = qb * BLK + r;
    const float4* qs4 = (const float4*)qs;

    for (int kb = 0; kb < MKB; ++kb) {
        const int kraw = skbi[qb * MKB + kb];
        const int jdx  = kraw > 0 ? kraw : 0;
        const bool vrow = (skbi[r * MKB + kb] >= 0);

        __syncthreads();
        {
            const size_t base = (size_t)(bi * SEQ + jdx * BLK) * DMODEL + coff;
            const float4* Kg = (const float4*)(K + base);
            const float4* Vg = (const float4*)(V + base);
            for (int idx = tid; idx < 64 * 24; idx += 256) {
                int rr = idx / 24, c4 = idx % 24;
                *(float4*)&ks[rr * KS_STRIDE + c4 * 4] =
                    Kg[(size_t)rr * (DMODEL / 4) + c4];
                *(float4*)&vs[rr * KS_STRIDE + c4 * 4] =
                    Vg[(size_t)rr * (DMODEL / 4) + c4];
            }
        }
        __syncthreads();

        float s[16];
        #pragma unroll
        for (int j = 0; j < 16; ++j) s[j] = 0.f;
        #pragma unroll 4
        for (int d4 = 0; d4 < 24; ++d4) {
            float4 qv = qs4[r * 24 + d4];
            #pragma unroll
            for (int j = 0; j < 16; ++j) {
                const int col = sub + 4 * j;
                float4 kv = *(const float4*)&ks[col * KS_STRIDE + d4 * 4];
                s[j] += qv.x * kv.x + qv.y * kv.y + qv.z * kv.z + qv.w * kv.w;
            }
        }

        float mloc = -INFINITY;
        #pragma unroll
        for (int j = 0; j < 16; ++j) {
            const int col  = sub + 4 * j;
            const int kpos = jdx * BLK + col;
            s[j] *= scale;
            if (!vrow || kpos > qpos) s[j] = -1e9f;
            mloc = fmaxf(mloc, s[j]);
        }
        mloc = fmaxf(mloc, __shfl_xor_sync(0xffffffffu, mloc, 1));
        mloc = fmaxf(mloc, __shfl_xor_sync(0xffffffffu, mloc, 2));

        const float mnew  = fmaxf(m_i, mloc);
        const float alpha = __expf(m_i - mnew);

        float psum = 0.f;
        #pragma unroll
        for (int j = 0; j < 16; ++j) {
            const float p = __expf(s[j] - mnew);
            ps[r * PS_STRIDE + sub + 4 * j] = p;
            psum += p;
        }
        psum += __shfl_xor_sync(0xffffffffu, psum, 1);
        psum += __shfl_xor_sync(0xffffffffu, psum, 2);

        l_i = l_i * alpha + psum;
        m_i = mnew;
        #pragma unroll
        for (int c = 0; c < 24; ++c) acc[c] *= alpha;

        __syncwarp();

        #pragma unroll 4
        for (int j = 0; j < 64; ++j) {
            const float p = ps[r * PS_STRIDE + j];
            #pragma unroll
            for (int c4 = 0; c4 < 6; ++c4) {
                float4 vv = *(const float4*)&vs[j * KS_STRIDE + sub * 24 + c4 * 4];
                acc[c4 * 4 + 0] += p * vv.x;
                acc[c4 * 4 + 1] += p * vv.y;
                acc[c4 * 4 + 2] += p * vv.z;
                acc[c4 * 4 + 3] += p * vv.w;
            }
        }
    }

    const float inv = 1.0f / l_i;
    float* Og = O + (size_t)(row0 + r) * DMODEL + coff + sub * 24;
    #pragma unroll
    for (int c4 = 0; c4 < 6; ++c4) {
        float4 v;
        v.x = acc[c4 * 4 + 0] * inv;
        v.y = acc[c4 * 4 + 1] * inv;
        v.z = acc[c4 * 4 + 2] * inv;
        v.w = acc[c4 * 4 + 3] * inv;
        *(float4*)(Og + c4 * 4) = v;
    }
}

// ---------------------------------------------------------------------------
// Launch
// ---------------------------------------------------------------------------
extern "C" void kernel_launch(void* const* d_in, const int* in_sizes, int n_in,
                              void* d_out, int out_size)
{
    const float* q     = (const float*)d_in[0];
    const float* ln1_g = (const float*)d_in[1];
    const float* ln1_b = (const float*)d_in[2];
    const float* Wq    = (const float*)d_in[3];
    const float* bq    = (const float*)d_in[4];
    const float* Wk    = (const float*)d_in[5];
    const float* bk    = (const float*)d_in[6];
    const float* Wv    = (const float*)d_in[7];
    const float* bv    = (const float*)d_in[8];
    const float* Wo    = (const float*)d_in[9];
    const float* bo    = (const float*)d_in[10];
    const float* ln2_g = (const float*)d_in[11];
    const float* ln2_b = (const float*)d_in[12];
    const float* W1    = (const float*)d_in[13];
    const float* b1    = (const float*)d_in[14];
    const float* W2    = (const float*)d_in[15];
    const float* b2    = (const float*)d_in[16];
    const int*   kbi   = (const int*)d_in[17];
    float* out = (float*)d_out;

    float *x1, *qb, *kb, *vb, *att, *xb, *hb, *gb;
    cudaGetSymbolAddress((void**)&x1,  g_x1);
    cudaGetSymbolAddress((void**)&qb,  g_q);
    cudaGetSymbolAddress((void**)&kb,  g_k);
    cudaGetSymbolAddress((void**)&vb,  g_v);
    cudaGetSymbolAddress((void**)&att, g_att);
    cudaGetSymbolAddress((void**)&xb,  g_x);
    cudaGetSymbolAddress((void**)&hb,  g_h);
    cudaGetSymbolAddress((void**)&gb,  g_ffn);

    const int ATTN_SMEM = (6144 + 6400 + 6400 + 4352) * 4;   // 93184 B
    cudaFuncSetAttribute(attn_kernel,
                         cudaFuncAttributeMaxDynamicSharedMemorySize, ATTN_SMEM);

    // 1. x1 = LN1(q)
    ln_kernel<<<ROWS, 256>>>(q, ln1_g, ln1_b, x1);

    // 2. Q,K,V projections (tf32 tensor cores)
    dim3 gp(DMODEL / 128, ROWS / 128);
    mma_gemm_kernel<false, false><<<gp, 256>>>(x1, Wq, bq, nullptr, qb, ROWS, DMODEL, DMODEL);
    mma_gemm_kernel<false, false><<<gp, 256>>>(x1, Wk, bk, nullptr, kb, ROWS, DMODEL, DMODEL);
    mma_gemm_kernel<false, false><<<gp, 256>>>(x1, Wv, bv, nullptr, vb, ROWS, DMODEL, DMODEL);

    // 3. BigBird attention
    attn_kernel<<<dim3(NBLOCKS, NHEAD, BATCH), 256, ATTN_SMEM>>>(qb, kb, vb, kbi, att);

    // 4. x = q + att @ Wo + bo
    mma_gemm_kernel<false, true><<<gp, 256>>>(att, Wo, bo, q, xb, ROWS, DMODEL, DMODEL);

    // 5. h = LN2(x)
    ln_kernel<<<ROWS, 256>>>(xb, ln2_g, ln2_b, hb);

    // 6. g = gelu(h @ W1 + b1)
    dim3 g1(DFF / 128, ROWS / 128);
    mma_gemm_kernel<true, false><<<g1, 256>>>(hb, W1, b1, nullptr, gb, ROWS, DFF, DMODEL);

    // 7. out = x + g @ W2 + b2
    mma_gemm_kernel<false, true><<<gp, 256>>>(gb, W2, b2, xb, out, ROWS, DMODEL, DFF);
}